// round 14
// baseline (speedup 1.0000x reference)
#include <cuda_runtime.h>
#include <cuda_bf16.h>
#include <stdint.h>

// ---------------------------------------------------------------------------
// Problem constants
// ---------------------------------------------------------------------------
#define BB   2
#define HH   12
#define DD   64
#define EE   768
#define QLL  1024
#define KLL  2048
#define HDD  768
#define SCALEF 0.125f
typedef int mask_t;
typedef unsigned short u16;

// ---------------------------------------------------------------------------
// Scratch (device globals)
// ---------------------------------------------------------------------------
#define XQ 0
#define XK ((size_t)2048 * 768)
#define XV ((size_t)6144 * 768)
#define XR ((size_t)10240 * 768)
#define XTOT ((size_t)12288 * 768)
__device__ u16 g_x_h[XTOT];
__device__ u16 g_x_l[XTOT];
#define WQO ((size_t)0)
#define WKO ((size_t)1 * 768 * 768)
#define WVO ((size_t)2 * 768 * 768)
#define WRO ((size_t)3 * 768 * 768)
#define WOO ((size_t)4 * 768 * 768)
__device__ u16 g_w_h[(size_t)5 * 768 * 768];
__device__ u16 g_w_l[(size_t)5 * 768 * 768];
__device__ u16 g_qw_h[(size_t)BB * QLL * HDD];
__device__ u16 g_qw_l[(size_t)BB * QLL * HDD];
__device__ u16 g_qr_h[(size_t)BB * QLL * HDD];
__device__ u16 g_qr_l[(size_t)BB * QLL * HDD];
__device__ u16 g_k_h [(size_t)BB * KLL * HDD];
__device__ u16 g_k_l [(size_t)BB * KLL * HDD];
__device__ u16 g_v_h [(size_t)BB * KLL * HDD];
__device__ u16 g_v_l [(size_t)BB * KLL * HDD];
__device__ u16 g_r_h [(size_t)KLL * HDD];
__device__ u16 g_r_l [(size_t)KLL * HDD];
__device__ u16 g_vec_h[(size_t)BB * QLL * HDD];
__device__ u16 g_vec_l[(size_t)BB * QLL * HDD];
__device__ float g_pv[3][(size_t)BB * QLL * HDD];
__device__ float g_s[(size_t)BB * HH * QLL * KLL];

// ---------------------------------------------------------------------------
// Primitives
// ---------------------------------------------------------------------------
__device__ __forceinline__ uint32_t smem_u32(const void* p) {
    uint32_t a;
    asm("{ .reg .u64 t; cvta.to.shared.u64 t, %1; cvt.u32.u64 %0, t; }" : "=r"(a) : "l"(p));
    return a;
}
__device__ __forceinline__ void ldsm4(uint32_t& r0, uint32_t& r1, uint32_t& r2, uint32_t& r3,
                                      uint32_t a) {
    asm volatile("ldmatrix.sync.aligned.m8n8.x4.shared.b16 {%0,%1,%2,%3}, [%4];"
                 : "=r"(r0), "=r"(r1), "=r"(r2), "=r"(r3) : "r"(a));
}
__device__ __forceinline__ void mma16816(float* c, const uint32_t* a, const uint32_t* b) {
    asm volatile("mma.sync.aligned.m16n8k16.row.col.f32.bf16.bf16.f32 "
                 "{%0,%1,%2,%3}, {%4,%5,%6,%7}, {%8,%9}, {%0,%1,%2,%3};"
                 : "+f"(c[0]), "+f"(c[1]), "+f"(c[2]), "+f"(c[3])
                 : "r"(a[0]), "r"(a[1]), "r"(a[2]), "r"(a[3]), "r"(b[0]), "r"(b[1]));
}
__device__ __forceinline__ void cpa16(uint32_t dst, const void* src) {
    asm volatile("cp.async.cg.shared.global [%0], [%1], 16;" :: "r"(dst), "l"(src));
}
#define CP_COMMIT() asm volatile("cp.async.commit_group;" ::: "memory")
#define CP_WAIT(n)  asm volatile("cp.async.wait_group %0;" :: "n"(n) : "memory")

__device__ __forceinline__ void split_bf16(float x, u16& h, u16& l) {
    __nv_bfloat16 hb = __float2bfloat16(x);
    h = __bfloat16_as_ushort(hb);
    l = __bfloat16_as_ushort(__float2bfloat16(x - __bfloat162float(hb)));
}
__device__ __forceinline__ void split4(float4 v, uint2& hi, uint2& lo) {
    u16 h0, h1, h2, h3, l0, l1, l2, l3;
    split_bf16(v.x, h0, l0); split_bf16(v.y, h1, l1);
    split_bf16(v.z, h2, l2); split_bf16(v.w, h3, l3);
    hi = make_uint2((uint32_t)h0 | ((uint32_t)h1 << 16), (uint32_t)h2 | ((uint32_t)h3 << 16));
    lo = make_uint2((uint32_t)l0 | ((uint32_t)l1 << 16), (uint32_t)l2 | ((uint32_t)l3 << 16));
}

// 32x32 warp tile (n-span 32 at nw offset)
template<int P>
__device__ __forceinline__ void warp_mma(uint32_t sb, uint32_t aHi, uint32_t aLo,
                                         uint32_t bHi, uint32_t bLo,
                                         int kcc, int mw, int nw, int lane,
                                         float acc[2][4][4])
{
    uint32_t ah[2][4], al[2][4], bh[4][2], bl[4][2];
    #pragma unroll
    for (int i = 0; i < 2; i++) {
        int row = mw * 32 + i * 16 + (lane & 15);
        int col = kcc + ((lane >> 4) << 3);
        uint32_t off = (uint32_t)(row * P + col * 2);
        ldsm4(ah[i][0], ah[i][1], ah[i][2], ah[i][3], sb + aHi + off);
        ldsm4(al[i][0], al[i][1], al[i][2], al[i][3], sb + aLo + off);
    }
    #pragma unroll
    for (int jj = 0; jj < 2; jj++) {
        int n = nw * 32 + jj * 16 + ((lane >> 4) << 3) + (lane & 7);
        int k = kcc + (((lane >> 3) & 1) << 3);
        uint32_t off = (uint32_t)(n * P + k * 2);
        ldsm4(bh[jj*2][0], bh[jj*2][1], bh[jj*2+1][0], bh[jj*2+1][1], sb + bHi + off);
        ldsm4(bl[jj*2][0], bl[jj*2][1], bl[jj*2+1][0], bl[jj*2+1][1], sb + bLo + off);
    }
    #pragma unroll
    for (int i = 0; i < 2; i++)
        #pragma unroll
        for (int j = 0; j < 4; j++)
            mma16816(acc[i][j], ah[i], bh[j]);
    #pragma unroll
    for (int i = 0; i < 2; i++)
        #pragma unroll
        for (int j = 0; j < 4; j++)
            mma16816(acc[i][j], ah[i], bl[j]);
    #pragma unroll
    for (int i = 0; i < 2; i++)
        #pragma unroll
        for (int j = 0; j < 4; j++)
            mma16816(acc[i][j], al[i], bh[j]);
}

// ---------------------------------------------------------------------------
// Converts (merged)
// ---------------------------------------------------------------------------
__global__ void cvt_all(const float* __restrict__ Q, const float* __restrict__ K,
                        const float* __restrict__ V, const float* __restrict__ pos)
{
    size_t i = ((size_t)blockIdx.x * 256 + threadIdx.x) * 4;
    const float* src; size_t off;
    if (i < XK)      { src = Q;   off = i; }
    else if (i < XV) { src = K;   off = i - XK; }
    else if (i < XR) { src = V;   off = i - XV; }
    else             { src = pos; off = i - XR; }
    float4 v = *reinterpret_cast<const float4*>(src + off);
    uint2 h, l; split4(v, h, l);
    *reinterpret_cast<uint2*>(g_x_h + i) = h;
    *reinterpret_cast<uint2*>(g_x_l + i) = l;
}

__global__ void cvtT_all(const float* __restrict__ Wq, const float* __restrict__ Wk,
                         const float* __restrict__ Wv, const float* __restrict__ Wr,
                         const float* __restrict__ Wo)
{
    __shared__ float t[32][33];
    const float* W;
    size_t wo;
    switch (blockIdx.z) {
        case 0: W = Wq; wo = WQO; break;
        case 1: W = Wk; wo = WKO; break;
        case 2: W = Wv; wo = WVO; break;
        case 3: W = Wr; wo = WRO; break;
        default: W = Wo; wo = WOO; break;
    }
    const int nb = blockIdx.x * 32, kb = blockIdx.y * 32;
    const int tx = threadIdx.x, ty = threadIdx.y;
    #pragma unroll
    for (int i = 0; i < 4; i++)
        t[ty + i * 8][tx] = W[(size_t)(kb + ty + i * 8) * 768 + nb + tx];
    __syncthreads();
    #pragma unroll
    for (int i = 0; i < 4; i++) {
        float v = t[tx][ty + i * 8];
        u16 h, l; split_bf16(v, h, l);
        size_t o = wo + (size_t)(nb + ty + i * 8) * 768 + kb + tx;
        g_w_h[o] = h; g_w_l[o] = l;
    }
}

__global__ void vecfin(u16* __restrict__ dh, u16* __restrict__ dl)
{
    int i = (blockIdx.x * blockDim.x + threadIdx.x) * 4;
    float4 a = *reinterpret_cast<const float4*>(&g_pv[0][i]);
    float4 b = *reinterpret_cast<const float4*>(&g_pv[1][i]);
    float4 c = *reinterpret_cast<const float4*>(&g_pv[2][i]);
    a.x += b.x + c.x; a.y += b.y + c.y; a.z += b.z + c.z; a.w += b.w + c.w;
    uint2 h, l; split4(a, h, l);
    *reinterpret_cast<uint2*>(dh + i) = h;
    *reinterpret_cast<uint2*>(dl + i) = l;
}

// ---------------------------------------------------------------------------
// Shared GEMM core: k-slab 32, 2-stage cp.async, 2 CTAs/SM, pitch 80B.
// ---------------------------------------------------------------------------
#define GP32 80
#define T2_AHI 0
#define T2_ALO (128 * GP32)
#define T2_BHI (2 * 128 * GP32)
#define T2_BLO (2 * 128 * GP32 + 64 * GP32)
#define T2_STAGE (2 * 128 * GP32 + 2 * 64 * GP32)  // 30720
#define T2_TOTAL (2 * T2_STAGE)                    // 61440

__device__ __forceinline__ void gemm_core(
    uint32_t sb, char* sm, int tid, int mw, int nw, int lane,
    const u16* Ah, const u16* Al, const u16* Bh, const u16* Bl,
    int m0, int n0, int K, float acc[2][4][4])
{
    const int nslab = K >> 5;
    auto issue = [&](int s, int st) {
        const uint32_t base = sb + st * T2_STAGE;
        const int k0 = s << 5;
        #pragma unroll
        for (int it = 0; it < 2; it++) {
            int id = it * 256 + tid;
            int m = id >> 2, c = id & 3;
            size_t src = (size_t)(m0 + m) * EE + k0 + c * 8;
            uint32_t dst = base + T2_AHI + m * GP32 + c * 16;
            cpa16(dst, Ah + src);
            cpa16(dst + (T2_ALO - T2_AHI), Al + src);
        }
        {
            int n = tid >> 2, c = tid & 3;
            size_t src = (size_t)(n0 + n) * EE + k0 + c * 8;
            uint32_t dst = base + T2_BHI + n * GP32 + c * 16;
            cpa16(dst, Bh + src);
            cpa16(dst + (T2_BLO - T2_BHI), Bl + src);
        }
    };

    issue(0, 0); CP_COMMIT();
    for (int s = 0; s < nslab; s++) {
        if (s + 1 < nslab) { issue(s + 1, (s + 1) & 1); CP_COMMIT(); CP_WAIT(1); }
        else               { CP_WAIT(0); }
        __syncthreads();
        const uint32_t st = (uint32_t)((s & 1) * T2_STAGE);
        #pragma unroll
        for (int ks = 0; ks < 2; ks++)
            warp_mma<GP32>(sb, st + T2_AHI, st + T2_ALO, st + T2_BHI, st + T2_BLO,
                           ks << 4, mw, nw, lane, acc);
        __syncthreads();
    }
}

// ---------------------------------------------------------------------------
// proj_all
// ---------------------------------------------------------------------------
__global__ void __launch_bounds__(256, 2)
proj_all(const float* __restrict__ bq, const float* __restrict__ bk,
         const float* __restrict__ bv,
         const float* __restrict__ rwb, const float* __restrict__ rrb)
{
    extern __shared__ char sm[];
    const uint32_t sb = smem_u32(sm);
    const int tid = threadIdx.x, wid = tid >> 5, lane = tid & 31;
    const int mw = wid >> 1, nw = wid & 1;
    const int n0 = blockIdx.x << 6;
    const int z = blockIdx.z;

    const u16 *Ah, *Al, *Bh, *Bl;
    u16 *C1h, *C1l, *C2h = nullptr, *C2l = nullptr;
    const float *bias, *add1 = nullptr, *add2 = nullptr;
    int m0, mode;
    if (z < 16) {
        Ah = g_x_h + XQ; Al = g_x_l + XQ; Bh = g_w_h + WQO; Bl = g_w_l + WQO;
        C1h = g_qw_h; C1l = g_qw_l; C2h = g_qr_h; C2l = g_qr_l;
        bias = bq; add1 = rwb; add2 = rrb; mode = 2; m0 = z << 7;
    } else if (z < 48) {
        Ah = g_x_h + XK; Al = g_x_l + XK; Bh = g_w_h + WKO; Bl = g_w_l + WKO;
        C1h = g_k_h; C1l = g_k_l; bias = bk; mode = 1; m0 = (z - 16) << 7;
    } else if (z < 80) {
        Ah = g_x_h + XV; Al = g_x_l + XV; Bh = g_w_h + WVO; Bl = g_w_l + WVO;
        C1h = g_v_h; C1l = g_v_l; bias = bv; mode = 1; m0 = (z - 48) << 7;
    } else {
        Ah = g_x_h + XR; Al = g_x_l + XR; Bh = g_w_h + WRO; Bl = g_w_l + WRO;
        C1h = g_r_h; C1l = g_r_l; bias = nullptr; mode = 1; m0 = (z - 80) << 7;
    }

    float acc[2][4][4] = {};
    gemm_core(sb, sm, tid, mw, nw, lane, Ah, Al, Bh, Bl, m0, n0, EE, acc);

    const int gid = lane >> 2, tg = lane & 3;
    #pragma unroll
    for (int i = 0; i < 2; i++)
        #pragma unroll
        for (int j = 0; j < 4; j++) {
            int c = n0 + nw * 32 + j * 8 + tg * 2;
            float b0 = bias ? bias[c] : 0.f;
            float b1 = bias ? bias[c + 1] : 0.f;
            #pragma unroll
            for (int eh = 0; eh < 2; eh++) {
                int r = m0 + mw * 32 + i * 16 + gid + 8 * eh;
                size_t base = (size_t)r * HDD + c;
                float v0 = acc[i][j][eh * 2 + 0] + b0;
                float v1 = acc[i][j][eh * 2 + 1] + b1;
                if (mode == 1) {
                    u16 h0, l0, h1, l1;
                    split_bf16(v0, h0, l0); split_bf16(v1, h1, l1);
                    *reinterpret_cast<uint32_t*>(C1h + base) = (uint32_t)h0 | ((uint32_t)h1 << 16);
                    *reinterpret_cast<uint32_t*>(C1l + base) = (uint32_t)l0 | ((uint32_t)l1 << 16);
                } else {
                    u16 h0, l0, h1, l1;
                    split_bf16(v0 + add1[c], h0, l0); split_bf16(v1 + add1[c + 1], h1, l1);
                    *reinterpret_cast<uint32_t*>(C1h + base) = (uint32_t)h0 | ((uint32_t)h1 << 16);
                    *reinterpret_cast<uint32_t*>(C1l + base) = (uint32_t)l0 | ((uint32_t)l1 << 16);
                    split_bf16(v0 + add2[c], h0, l0); split_bf16(v1 + add2[c + 1], h1, l1);
                    *reinterpret_cast<uint32_t*>(C2h + base) = (uint32_t)h0 | ((uint32_t)h1 << 16);
                    *reinterpret_cast<uint32_t*>(C2l + base) = (uint32_t)l0 | ((uint32_t)l1 << 16);
                }
            }
        }
}

// ---------------------------------------------------------------------------
// out-proj
// ---------------------------------------------------------------------------
__global__ void __launch_bounds__(256, 2)
outproj(const float* __restrict__ bo, float* __restrict__ Cf)
{
    extern __shared__ char sm[];
    const uint32_t sb = smem_u32(sm);
    const int tid = threadIdx.x, wid = tid >> 5, lane = tid & 31;
    const int mw = wid >> 1, nw = wid & 1;
    const int m0 = blockIdx.y << 7;
    const int n0 = blockIdx.x << 6;

    float acc[2][4][4] = {};
    gemm_core(sb, sm, tid, mw, nw, lane, g_vec_h, g_vec_l,
              g_w_h + WOO, g_w_l + WOO, m0, n0, HDD, acc);

    const int gid = lane >> 2, tg = lane & 3;
    #pragma unroll
    for (int i = 0; i < 2; i++)
        #pragma unroll
        for (int j = 0; j < 4; j++) {
            int c = n0 + nw * 32 + j * 8 + tg * 2;
            float b0 = bo[c], b1 = bo[c + 1];
            #pragma unroll
            for (int eh = 0; eh < 2; eh++) {
                int r = m0 + mw * 32 + i * 16 + gid + 8 * eh;
                *reinterpret_cast<float2*>(Cf + (size_t)r * EE + c) =
                    make_float2(acc[i][j][eh * 2 + 0] + b0, acc[i][j][eh * 2 + 1] + b1);
            }
        }
}

// ---------------------------------------------------------------------------
// tscore v4: 512 threads / 16 warps (4m x 4n, 32x32 warp tiles), A' 128x128
// resident, 128-key B tiles, 2-stage cp.async ring.  208.9KB smem, occ 1
// (16 warps/SM), 24.6 FLOP per LDS byte.
// ---------------------------------------------------------------------------
#define SP 272
#define TS_AHI 0
#define TS_ALO (128 * SP)
#define TS_B   (2 * 128 * SP)       // 69632
#define TS_BSTG (2 * 128 * SP)      // 69632 per stage (hi+lo)
#define TS_BLOD (128 * SP)          // 34816
#define TS_TOTAL (TS_B + 2 * TS_BSTG)   // 208896
#define NKT 16                      // 16 key-tiles of 128

__global__ void __launch_bounds__(512, 1)
tscore()
{
    extern __shared__ char sm[];
    const uint32_t sb = smem_u32(sm);
    const int tid = threadIdx.x, wid = tid >> 5, lane = tid & 31;
    const int mw = wid >> 2, nw = wid & 3;
    const int gid = lane >> 2, tg = lane & 3;
    const int bh = blockIdx.z;
    const int b3 = bh / HH, h3 = bh % HH;
    const int mp = bh + BB;
    const int bu = mp / (HH + 1), hh = mp % (HH + 1);
    const int has_bd = (hh != 0);
    const int hm1 = hh - 1;
    const int q0 = blockIdx.y << 7;
    const int ksp = blockIdx.x;
    const int kt0 = (ksp * NKT) / 3, kt1 = ((ksp + 1) * NKT) / 3;

    // A' fill (128 q-rows x 128 d), once  (2048 16B-chunks / 512 threads)
    #pragma unroll
    for (int it = 0; it < 4; it++) {
        int id = it * 512 + tid;
        int m = id >> 4, c = id & 15;
        uint4 hv, lv;
        if (c < 8) {
            size_t src = (size_t)(b3 * QLL + q0 + m) * HDD + h3 * DD + c * 8;
            hv = *reinterpret_cast<const uint4*>(g_qw_h + src);
            lv = *reinterpret_cast<const uint4*>(g_qw_l + src);
        } else if (has_bd) {
            size_t src = (size_t)(bu * QLL + q0 + m) * HDD + hm1 * DD + (c - 8) * 8;
            hv = *reinterpret_cast<const uint4*>(g_qr_h + src);
            lv = *reinterpret_cast<const uint4*>(g_qr_l + src);
        } else {
            hv = make_uint4(0u, 0u, 0u, 0u); lv = hv;
        }
        int off = m * SP + c * 16;
        *reinterpret_cast<uint4*>(sm + TS_AHI + off) = hv;
        *reinterpret_cast<uint4*>(sm + TS_ALO + off) = lv;
    }
    // Zero B' second halves (never cp.async'd when !has_bd)
    if (!has_bd) {
        uint4 z = make_uint4(0u, 0u, 0u, 0u);
        for (int id = tid; id < 128 * 8; id += 512) {
            int n = id >> 3, c = id & 7;
            int o = TS_B + n * SP + 128 + c * 16;
            *reinterpret_cast<uint4*>(sm + o) = z;
            *reinterpret_cast<uint4*>(sm + o + TS_BLOD) = z;
            *reinterpret_cast<uint4*>(sm + o + TS_BSTG) = z;
            *reinterpret_cast<uint4*>(sm + o + TS_BSTG + TS_BLOD) = z;
        }
    }

    auto issueB = [&](int kt, int st) {
        const uint32_t base = sb + TS_B + st * TS_BSTG;
        const int kc = kt << 7;
        const int nch = has_bd ? 16 : 8;
        const int tot = 128 * nch;
        for (int id = tid; id < tot; id += 512) {
            int n = id / nch, c = id % nch;
            uint32_t dst = base + n * SP + c * 16;
            if (c < 8) {
                size_t src = (size_t)(b3 * KLL + kc + n) * HDD + h3 * DD + c * 8;
                cpa16(dst, g_k_h + src);
                cpa16(dst + TS_BLOD, g_k_l + src);
            } else {
                size_t src = (size_t)(kc + n) * HDD + hm1 * DD + (c - 8) * 8;
                cpa16(dst, g_r_h + src);
                cpa16(dst + TS_BLOD, g_r_l + src);
            }
        }
    };

    issueB(kt0, 0); CP_COMMIT();

    for (int kt = kt0; kt < kt1; kt++) {
        const int stg = (kt - kt0) & 1;
        if (kt + 1 < kt1) { issueB(kt + 1, stg ^ 1); CP_COMMIT(); CP_WAIT(1); }
        else              { CP_WAIT(0); }
        __syncthreads();

        float acc[2][4][4] = {};
        const uint32_t bst = (uint32_t)(TS_B + stg * TS_BSTG);
        #pragma unroll
        for (int ks = 0; ks < 8; ks++)
            warp_mma<SP>(sb, TS_AHI, TS_ALO, bst, bst + TS_BLOD,
                         ks << 4, mw, nw, lane, acc);

        const int kc = kt << 7;
        #pragma unroll
        for (int i = 0; i < 2; i++)
            #pragma unroll
            for (int j = 0; j < 4; j++) {
                int q = q0 + mw * 32 + i * 16 + gid;
                int c = kc + nw * 32 + j * 8 + tg * 2;
                const size_t srow0 = ((size_t)bh * QLL + q) * KLL + c;
                *reinterpret_cast<float2*>(g_s + srow0) =
                    make_float2(acc[i][j][0] * SCALEF, acc[i][j][1] * SCALEF);
                *reinterpret_cast<float2*>(g_s + srow0 + 8 * KLL) =
                    make_float2(acc[i][j][2] * SCALEF, acc[i][j][3] * SCALEF);
            }
        __syncthreads();
    }
}

// ---------------------------------------------------------------------------
// Softmax: reads int32 mask directly (streaming, HBM-roofline)
// ---------------------------------------------------------------------------
__device__ __forceinline__ float warp_max(float v) {
    #pragma unroll
    for (int o = 16; o; o >>= 1) v = fmaxf(v, __shfl_xor_sync(0xffffffffu, v, o));
    return v;
}
__device__ __forceinline__ float warp_sum(float v) {
    #pragma unroll
    for (int o = 16; o; o >>= 1) v += __shfl_xor_sync(0xffffffffu, v, o);
    return v;
}

__global__ __launch_bounds__(256)
void softmax_kernel(const float* __restrict__ S, float* __restrict__ P,
                    const mask_t* __restrict__ mask)
{
    const size_t row = blockIdx.x;
    const int b3 = (int)(row / (HH * QLL));
    const int q  = (int)(row % QLL);
    const float* s = S + row * KLL;
    float*       p = P + row * KLL;
    const int tid = threadIdx.x;

    __shared__ float sh[8];
    const int wid = tid >> 5;
    const int lid = tid & 31;

    const mask_t* mrow = mask + ((size_t)b3 * QLL + q) * KLL + tid * 8;
    int4 mk0 = *reinterpret_cast<const int4*>(mrow);
    int4 mk1 = *reinterpret_cast<const int4*>(mrow + 4);

    float v[8];
    *reinterpret_cast<float4*>(v)     = *reinterpret_cast<const float4*>(s + tid * 8);
    *reinterpret_cast<float4*>(v + 4) = *reinterpret_cast<const float4*>(s + tid * 8 + 4);

    if (mk0.x) v[0] = -3.0e38f;
    if (mk0.y) v[1] = -3.0e38f;
    if (mk0.z) v[2] = -3.0e38f;
    if (mk0.w) v[3] = -3.0e38f;
    if (mk1.x) v[4] = -3.0e38f;
    if (mk1.y) v[5] = -3.0e38f;
    if (mk1.z) v[6] = -3.0e38f;
    if (mk1.w) v[7] = -3.0e38f;

    float m = -3.0e38f;
    #pragma unroll
    for (int i = 0; i < 8; i++) m = fmaxf(m, v[i]);
    float wm = warp_max(m);
    if (lid == 0) sh[wid] = wm;
    __syncthreads();
    if (wid == 0) {
        float t = (lid < 8) ? sh[lid] : -3.0e38f;
        t = warp_max(t);
        if (lid == 0) sh[0] = t;
    }
    __syncthreads();
    const float bm = sh[0];

    float lsum = 0.0f;
    #pragma unroll
    for (int i = 0; i < 8; i++) {
        v[i] = __expf(v[i] - bm);
        lsum += v[i];
    }
    float ws = warp_sum(lsum);
    __syncthreads();
    if (lid == 0) sh[wid] = ws;
    __syncthreads();
    if (wid == 0) {
        float t = (lid < 8) ? sh[lid] : 0.0f;
        t = warp_sum(t);
        if (lid == 0) sh[0] = t;
    }
    __syncthreads();
    const float inv = 1.0f / sh[0];

    #pragma unroll
    for (int i = 0; i < 8; i++) v[i] *= inv;
    *reinterpret_cast<float4*>(p + tid * 8)     = *reinterpret_cast<float4*>(v);
    *reinterpret_cast<float4*>(p + tid * 8 + 4) = *reinterpret_cast<float4*>(v + 4);
}

// ---------------------------------------------------------------------------
// pv: vec_partial[ksp] = prob tile @ V_h  (3-way k-split, fp32 out)
// ---------------------------------------------------------------------------
#define GP 144
#define PV_AHI 0
#define PV_ALO (128 * GP)
#define PV_BHI (2 * 128 * GP)
#define PV_BLO (2 * 128 * GP + 64 * GP)
#define PV_TOTAL (2 * 128 * GP + 2 * 64 * GP)   // 55296

__global__ void __launch_bounds__(256, 2)
pv_kernel(const float* __restrict__ prob)
{
    extern __shared__ char sm[];
    const uint32_t sb = smem_u32(sm);
    const int tid = threadIdx.x, wid = tid >> 5, lane = tid & 31;
    const int mw = wid >> 1, nw = wid & 1;
    const int bh = blockIdx.z;
    const int b3 = bh / HH, h3 = bh % HH;
    const int q0 = blockIdx.y << 7;
    const int ksp = blockIdx.x;
    const int kt0 = (ksp * 32) / 3, kt1 = ((ksp + 1) * 32) / 3;

    float acc[2][4][4] = {};

    for (int kt = kt0; kt < kt1; kt++) {
        const int kc = kt << 6;
        #pragma unroll
        for (int it = 0; it < 8; it++) {
            int idx = (it * 256 + tid) << 2;
            int m = idx >> 6, k = idx & 63;
            float4 p4 = *reinterpret_cast<const float4*>(
                prob + ((size_t)bh * QLL + q0 + m) * KLL + kc + k);
            uint2 hi, lo; split4(p4, hi, lo);
            int off = m * GP + k * 2;
            *reinterpret_cast<uint2*>(sm + PV_AHI + off) = hi;
            *reinterpret_cast<uint2*>(sm + PV_ALO + off) = lo;
        }
        #pragma unroll
        for (int it = 0; it < 16; it++) {
            int idx = it * 256 + tid;
            int k = idx >> 6, n = idx & 63;
            size_t base = (size_t)(b3 * KLL + kc + k) * HDD + h3 * DD + n;
            int off = n * GP + k * 2;
            *reinterpret_cast<u16*>(sm + PV_BHI + off) = g_v_h[base];
            *reinterpret_cast<u16*>(sm + PV_BLO + off) = g_v_l[base];
        }
        __syncthreads();
        #pragma unroll
        for (int ks = 0; ks < 4; ks++)
            warp_mma<GP>(sb, PV_AHI, PV_ALO, PV_BHI, PV_BLO, ks << 4, mw, nw, lane, acc);
        __syncthreads();
    }

    float* dst = g_pv[ksp];
    const int gid = lane >> 2, tg = lane & 3;
    #pragma unroll
    for (int i = 0; i < 2; i++)
        #pragma unroll
        for (int j = 0; j < 4; j++) {
            int c = nw * 32 + j * 8 + tg * 2;
            #pragma unroll
            for (int eh = 0; eh < 2; eh++) {
                int q = q0 + mw * 32 + i * 16 + gid + 8 * eh;
                *reinterpret_cast<float2*>(
                    dst + (size_t)(b3 * QLL + q) * HDD + h3 * DD + c) =
                    make_float2(acc[i][j][eh * 2 + 0], acc[i][j][eh * 2 + 1]);
            }
        }
}

// ---------------------------------------------------------------------------
// Launch
// ---------------------------------------------------------------------------
extern "C" void kernel_launch(void* const* d_in, const int* in_sizes, int n_in,
                              void* d_out, int out_size)
{
    (void)in_sizes; (void)n_in; (void)out_size;

    const float*  Q    = (const float*)d_in[0];
    const float*  Kin  = (const float*)d_in[1];
    const float*  Vin  = (const float*)d_in[2];
    const float*  pos  = (const float*)d_in[3];
    const float*  rwb  = (const float*)d_in[4];
    const float*  rrb  = (const float*)d_in[5];
    const mask_t* mask = (const mask_t*)d_in[6];
    const float*  Wq = (const float*)d_in[8];
    const float*  bq = (const float*)d_in[9];
    const float*  Wk = (const float*)d_in[10];
    const float*  bk = (const float*)d_in[11];
    const float*  Wv = (const float*)d_in[12];
    const float*  bv = (const float*)d_in[13];
    const float*  Wr = (const float*)d_in[14];
    const float*  Wo = (const float*)d_in[15];
    const float*  bo = (const float*)d_in[16];

    float* out  = (float*)d_out;
    float* prob = out + (size_t)BB * QLL * EE;

    u16 *vech, *vecl;
    float *ps;
    cudaGetSymbolAddress((void**)&vech, g_vec_h);
    cudaGetSymbolAddress((void**)&vecl, g_vec_l);
    cudaGetSymbolAddress((void**)&ps,  g_s);

    cudaFuncSetAttribute(proj_all,  cudaFuncAttributeMaxDynamicSharedMemorySize, T2_TOTAL);
    cudaFuncSetAttribute(outproj,   cudaFuncAttributeMaxDynamicSharedMemorySize, T2_TOTAL);
    cudaFuncSetAttribute(tscore,    cudaFuncAttributeMaxDynamicSharedMemorySize, TS_TOTAL);
    cudaFuncSetAttribute(pv_kernel, cudaFuncAttributeMaxDynamicSharedMemorySize, PV_TOTAL);

    const dim3 blk(256);

    // Converts (2 launches)
    cvt_all<<<XTOT / 1024, blk>>>(Q, Kin, Vin, pos);
    cvtT_all<<<dim3(24, 24, 5), dim3(32, 8)>>>(Wq, Wk, Wv, Wr, Wo);

    // All four projections in one launch
    proj_all<<<dim3(12, 1, 96), blk, T2_TOTAL>>>(bq, bk, bv, rwb, rrb);

    // Scores (raw, scaled), 3-way k-split, 16-warp CTAs, 128-key tiles
    tscore<<<dim3(3, QLL / 128, BB * HH), dim3(512), TS_TOTAL>>>();

    // Softmax (mask read directly) -> prob
    softmax_kernel<<<BB * HH * QLL, blk>>>(ps, prob, mask);

    // PV (3-way k-split) + reduce/split
    pv_kernel<<<dim3(3, QLL / 128, BB * HH), blk, PV_TOTAL>>>(prob);
    vecfin<<<(BB * QLL * HDD) / 1024, blk>>>(vech, vecl);

    // Output projection
    outproj<<<dim3(12, 16), blk, T2_TOTAL>>>(bo, out);
}

// round 15
// speedup vs baseline: 1.0239x; 1.0239x over previous
#include <cuda_runtime.h>
#include <cuda_bf16.h>
#include <stdint.h>

// ---------------------------------------------------------------------------
// Problem constants
// ---------------------------------------------------------------------------
#define BB   2
#define HH   12
#define DD   64
#define EE   768
#define QLL  1024
#define KLL  2048
#define HDD  768
#define SCALEF 0.125f
typedef int mask_t;
typedef unsigned short u16;

// ---------------------------------------------------------------------------
// Scratch (device globals)
// ---------------------------------------------------------------------------
#define XQ 0
#define XK ((size_t)2048 * 768)
#define XV ((size_t)6144 * 768)
#define XR ((size_t)10240 * 768)
#define XTOT ((size_t)12288 * 768)
__device__ u16 g_x_h[XTOT];
__device__ u16 g_x_l[XTOT];
#define WQO ((size_t)0)
#define WKO ((size_t)1 * 768 * 768)
#define WVO ((size_t)2 * 768 * 768)
#define WRO ((size_t)3 * 768 * 768)
#define WOO ((size_t)4 * 768 * 768)
__device__ u16 g_w_h[(size_t)5 * 768 * 768];
__device__ u16 g_w_l[(size_t)5 * 768 * 768];
__device__ u16 g_qw_h[(size_t)BB * QLL * HDD];
__device__ u16 g_qw_l[(size_t)BB * QLL * HDD];
__device__ u16 g_qr_h[(size_t)BB * QLL * HDD];
__device__ u16 g_qr_l[(size_t)BB * QLL * HDD];
__device__ u16 g_k_h [(size_t)BB * KLL * HDD];
__device__ u16 g_k_l [(size_t)BB * KLL * HDD];
__device__ u16 g_v_h [(size_t)BB * KLL * HDD];
__device__ u16 g_v_l [(size_t)BB * KLL * HDD];
__device__ u16 g_r_h [(size_t)KLL * HDD];
__device__ u16 g_r_l [(size_t)KLL * HDD];
__device__ u16 g_vec_h[(size_t)BB * QLL * HDD];
__device__ u16 g_vec_l[(size_t)BB * QLL * HDD];
__device__ float g_pv[3][(size_t)BB * QLL * HDD];
__device__ float g_s[(size_t)BB * HH * QLL * KLL];

// ---------------------------------------------------------------------------
// Primitives
// ---------------------------------------------------------------------------
__device__ __forceinline__ uint32_t smem_u32(const void* p) {
    uint32_t a;
    asm("{ .reg .u64 t; cvta.to.shared.u64 t, %1; cvt.u32.u64 %0, t; }" : "=r"(a) : "l"(p));
    return a;
}
__device__ __forceinline__ void ldsm4(uint32_t& r0, uint32_t& r1, uint32_t& r2, uint32_t& r3,
                                      uint32_t a) {
    asm volatile("ldmatrix.sync.aligned.m8n8.x4.shared.b16 {%0,%1,%2,%3}, [%4];"
                 : "=r"(r0), "=r"(r1), "=r"(r2), "=r"(r3) : "r"(a));
}
__device__ __forceinline__ void mma16816(float* c, const uint32_t* a, const uint32_t* b) {
    asm volatile("mma.sync.aligned.m16n8k16.row.col.f32.bf16.bf16.f32 "
                 "{%0,%1,%2,%3}, {%4,%5,%6,%7}, {%8,%9}, {%0,%1,%2,%3};"
                 : "+f"(c[0]), "+f"(c[1]), "+f"(c[2]), "+f"(c[3])
                 : "r"(a[0]), "r"(a[1]), "r"(a[2]), "r"(a[3]), "r"(b[0]), "r"(b[1]));
}
__device__ __forceinline__ void cpa16(uint32_t dst, const void* src) {
    asm volatile("cp.async.cg.shared.global [%0], [%1], 16;" :: "r"(dst), "l"(src));
}
#define CP_COMMIT() asm volatile("cp.async.commit_group;" ::: "memory")
#define CP_WAIT(n)  asm volatile("cp.async.wait_group %0;" :: "n"(n) : "memory")

__device__ __forceinline__ void split_bf16(float x, u16& h, u16& l) {
    __nv_bfloat16 hb = __float2bfloat16(x);
    h = __bfloat16_as_ushort(hb);
    l = __bfloat16_as_ushort(__float2bfloat16(x - __bfloat162float(hb)));
}
__device__ __forceinline__ void split4(float4 v, uint2& hi, uint2& lo) {
    u16 h0, h1, h2, h3, l0, l1, l2, l3;
    split_bf16(v.x, h0, l0); split_bf16(v.y, h1, l1);
    split_bf16(v.z, h2, l2); split_bf16(v.w, h3, l3);
    hi = make_uint2((uint32_t)h0 | ((uint32_t)h1 << 16), (uint32_t)h2 | ((uint32_t)h3 << 16));
    lo = make_uint2((uint32_t)l0 | ((uint32_t)l1 << 16), (uint32_t)l2 | ((uint32_t)l3 << 16));
}

// 32x32 warp tile (n-span 32 at nw offset)
template<int P>
__device__ __forceinline__ void warp_mma(uint32_t sb, uint32_t aHi, uint32_t aLo,
                                         uint32_t bHi, uint32_t bLo,
                                         int kcc, int mw, int nw, int lane,
                                         float acc[2][4][4])
{
    uint32_t ah[2][4], al[2][4], bh[4][2], bl[4][2];
    #pragma unroll
    for (int i = 0; i < 2; i++) {
        int row = mw * 32 + i * 16 + (lane & 15);
        int col = kcc + ((lane >> 4) << 3);
        uint32_t off = (uint32_t)(row * P + col * 2);
        ldsm4(ah[i][0], ah[i][1], ah[i][2], ah[i][3], sb + aHi + off);
        ldsm4(al[i][0], al[i][1], al[i][2], al[i][3], sb + aLo + off);
    }
    #pragma unroll
    for (int jj = 0; jj < 2; jj++) {
        int n = nw * 32 + jj * 16 + ((lane >> 4) << 3) + (lane & 7);
        int k = kcc + (((lane >> 3) & 1) << 3);
        uint32_t off = (uint32_t)(n * P + k * 2);
        ldsm4(bh[jj*2][0], bh[jj*2][1], bh[jj*2+1][0], bh[jj*2+1][1], sb + bHi + off);
        ldsm4(bl[jj*2][0], bl[jj*2][1], bl[jj*2+1][0], bl[jj*2+1][1], sb + bLo + off);
    }
    #pragma unroll
    for (int i = 0; i < 2; i++)
        #pragma unroll
        for (int j = 0; j < 4; j++)
            mma16816(acc[i][j], ah[i], bh[j]);
    #pragma unroll
    for (int i = 0; i < 2; i++)
        #pragma unroll
        for (int j = 0; j < 4; j++)
            mma16816(acc[i][j], ah[i], bl[j]);
    #pragma unroll
    for (int i = 0; i < 2; i++)
        #pragma unroll
        for (int j = 0; j < 4; j++)
            mma16816(acc[i][j], al[i], bh[j]);
}

// 32x16 warp tile (n=16/warp) — tscore's 32-key B tiles
template<int P>
__device__ __forceinline__ void warp_mma_n16(uint32_t sb, uint32_t aHi, uint32_t aLo,
                                             uint32_t bHi, uint32_t bLo,
                                             int kcc, int mw, int nw, int lane,
                                             float acc[2][2][4])
{
    uint32_t ah[2][4], al[2][4], bh[2][2], bl[2][2];
    #pragma unroll
    for (int i = 0; i < 2; i++) {
        int row = mw * 32 + i * 16 + (lane & 15);
        int col = kcc + ((lane >> 4) << 3);
        uint32_t off = (uint32_t)(row * P + col * 2);
        ldsm4(ah[i][0], ah[i][1], ah[i][2], ah[i][3], sb + aHi + off);
        ldsm4(al[i][0], al[i][1], al[i][2], al[i][3], sb + aLo + off);
    }
    {
        int n = nw * 16 + ((lane >> 4) << 3) + (lane & 7);
        int k = kcc + (((lane >> 3) & 1) << 3);
        uint32_t off = (uint32_t)(n * P + k * 2);
        ldsm4(bh[0][0], bh[0][1], bh[1][0], bh[1][1], sb + bHi + off);
        ldsm4(bl[0][0], bl[0][1], bl[1][0], bl[1][1], sb + bLo + off);
    }
    #pragma unroll
    for (int i = 0; i < 2; i++)
        #pragma unroll
        for (int j = 0; j < 2; j++)
            mma16816(acc[i][j], ah[i], bh[j]);
    #pragma unroll
    for (int i = 0; i < 2; i++)
        #pragma unroll
        for (int j = 0; j < 2; j++)
            mma16816(acc[i][j], ah[i], bl[j]);
    #pragma unroll
    for (int i = 0; i < 2; i++)
        #pragma unroll
        for (int j = 0; j < 2; j++)
            mma16816(acc[i][j], al[i], bh[j]);
}

// ---------------------------------------------------------------------------
// Converts (merged)
// ---------------------------------------------------------------------------
__global__ void cvt_all(const float* __restrict__ Q, const float* __restrict__ K,
                        const float* __restrict__ V, const float* __restrict__ pos)
{
    size_t i = ((size_t)blockIdx.x * 256 + threadIdx.x) * 4;
    const float* src; size_t off;
    if (i < XK)      { src = Q;   off = i; }
    else if (i < XV) { src = K;   off = i - XK; }
    else if (i < XR) { src = V;   off = i - XV; }
    else             { src = pos; off = i - XR; }
    float4 v = *reinterpret_cast<const float4*>(src + off);
    uint2 h, l; split4(v, h, l);
    *reinterpret_cast<uint2*>(g_x_h + i) = h;
    *reinterpret_cast<uint2*>(g_x_l + i) = l;
}

__global__ void cvtT_all(const float* __restrict__ Wq, const float* __restrict__ Wk,
                         const float* __restrict__ Wv, const float* __restrict__ Wr,
                         const float* __restrict__ Wo)
{
    __shared__ float t[32][33];
    const float* W;
    size_t wo;
    switch (blockIdx.z) {
        case 0: W = Wq; wo = WQO; break;
        case 1: W = Wk; wo = WKO; break;
        case 2: W = Wv; wo = WVO; break;
        case 3: W = Wr; wo = WRO; break;
        default: W = Wo; wo = WOO; break;
    }
    const int nb = blockIdx.x * 32, kb = blockIdx.y * 32;
    const int tx = threadIdx.x, ty = threadIdx.y;
    #pragma unroll
    for (int i = 0; i < 4; i++)
        t[ty + i * 8][tx] = W[(size_t)(kb + ty + i * 8) * 768 + nb + tx];
    __syncthreads();
    #pragma unroll
    for (int i = 0; i < 4; i++) {
        float v = t[tx][ty + i * 8];
        u16 h, l; split_bf16(v, h, l);
        size_t o = wo + (size_t)(nb + ty + i * 8) * 768 + kb + tx;
        g_w_h[o] = h; g_w_l[o] = l;
    }
}

__global__ void vecfin(u16* __restrict__ dh, u16* __restrict__ dl)
{
    int i = (blockIdx.x * blockDim.x + threadIdx.x) * 4;
    float4 a = *reinterpret_cast<const float4*>(&g_pv[0][i]);
    float4 b = *reinterpret_cast<const float4*>(&g_pv[1][i]);
    float4 c = *reinterpret_cast<const float4*>(&g_pv[2][i]);
    a.x += b.x + c.x; a.y += b.y + c.y; a.z += b.z + c.z; a.w += b.w + c.w;
    uint2 h, l; split4(a, h, l);
    *reinterpret_cast<uint2*>(dh + i) = h;
    *reinterpret_cast<uint2*>(dl + i) = l;
}

// ---------------------------------------------------------------------------
// Shared GEMM core: k-slab 32, 2-stage cp.async, 2 CTAs/SM, pitch 80B.
// ---------------------------------------------------------------------------
#define GP32 80
#define T2_AHI 0
#define T2_ALO (128 * GP32)
#define T2_BHI (2 * 128 * GP32)
#define T2_BLO (2 * 128 * GP32 + 64 * GP32)
#define T2_STAGE (2 * 128 * GP32 + 2 * 64 * GP32)  // 30720
#define T2_TOTAL (2 * T2_STAGE)                    // 61440

__device__ __forceinline__ void gemm_core(
    uint32_t sb, char* sm, int tid, int mw, int nw, int lane,
    const u16* Ah, const u16* Al, const u16* Bh, const u16* Bl,
    int m0, int n0, int K, float acc[2][4][4])
{
    const int nslab = K >> 5;
    auto issue = [&](int s, int st) {
        const uint32_t base = sb + st * T2_STAGE;
        const int k0 = s << 5;
        #pragma unroll
        for (int it = 0; it < 2; it++) {
            int id = it * 256 + tid;
            int m = id >> 2, c = id & 3;
            size_t src = (size_t)(m0 + m) * EE + k0 + c * 8;
            uint32_t dst = base + T2_AHI + m * GP32 + c * 16;
            cpa16(dst, Ah + src);
            cpa16(dst + (T2_ALO - T2_AHI), Al + src);
        }
        {
            int n = tid >> 2, c = tid & 3;
            size_t src = (size_t)(n0 + n) * EE + k0 + c * 8;
            uint32_t dst = base + T2_BHI + n * GP32 + c * 16;
            cpa16(dst, Bh + src);
            cpa16(dst + (T2_BLO - T2_BHI), Bl + src);
        }
    };

    issue(0, 0); CP_COMMIT();
    for (int s = 0; s < nslab; s++) {
        if (s + 1 < nslab) { issue(s + 1, (s + 1) & 1); CP_COMMIT(); CP_WAIT(1); }
        else               { CP_WAIT(0); }
        __syncthreads();
        const uint32_t st = (uint32_t)((s & 1) * T2_STAGE);
        #pragma unroll
        for (int ks = 0; ks < 2; ks++)
            warp_mma<GP32>(sb, st + T2_AHI, st + T2_ALO, st + T2_BHI, st + T2_BLO,
                           ks << 4, mw, nw, lane, acc);
        __syncthreads();
    }
}

// ---------------------------------------------------------------------------
// proj_all
// ---------------------------------------------------------------------------
__global__ void __launch_bounds__(256, 2)
proj_all(const float* __restrict__ bq, const float* __restrict__ bk,
         const float* __restrict__ bv,
         const float* __restrict__ rwb, const float* __restrict__ rrb)
{
    extern __shared__ char sm[];
    const uint32_t sb = smem_u32(sm);
    const int tid = threadIdx.x, wid = tid >> 5, lane = tid & 31;
    const int mw = wid >> 1, nw = wid & 1;
    const int n0 = blockIdx.x << 6;
    const int z = blockIdx.z;

    const u16 *Ah, *Al, *Bh, *Bl;
    u16 *C1h, *C1l, *C2h = nullptr, *C2l = nullptr;
    const float *bias, *add1 = nullptr, *add2 = nullptr;
    int m0, mode;
    if (z < 16) {
        Ah = g_x_h + XQ; Al = g_x_l + XQ; Bh = g_w_h + WQO; Bl = g_w_l + WQO;
        C1h = g_qw_h; C1l = g_qw_l; C2h = g_qr_h; C2l = g_qr_l;
        bias = bq; add1 = rwb; add2 = rrb; mode = 2; m0 = z << 7;
    } else if (z < 48) {
        Ah = g_x_h + XK; Al = g_x_l + XK; Bh = g_w_h + WKO; Bl = g_w_l + WKO;
        C1h = g_k_h; C1l = g_k_l; bias = bk; mode = 1; m0 = (z - 16) << 7;
    } else if (z < 80) {
        Ah = g_x_h + XV; Al = g_x_l + XV; Bh = g_w_h + WVO; Bl = g_w_l + WVO;
        C1h = g_v_h; C1l = g_v_l; bias = bv; mode = 1; m0 = (z - 48) << 7;
    } else {
        Ah = g_x_h + XR; Al = g_x_l + XR; Bh = g_w_h + WRO; Bl = g_w_l + WRO;
        C1h = g_r_h; C1l = g_r_l; bias = nullptr; mode = 1; m0 = (z - 80) << 7;
    }

    float acc[2][4][4] = {};
    gemm_core(sb, sm, tid, mw, nw, lane, Ah, Al, Bh, Bl, m0, n0, EE, acc);

    const int gid = lane >> 2, tg = lane & 3;
    #pragma unroll
    for (int i = 0; i < 2; i++)
        #pragma unroll
        for (int j = 0; j < 4; j++) {
            int c = n0 + nw * 32 + j * 8 + tg * 2;
            float b0 = bias ? bias[c] : 0.f;
            float b1 = bias ? bias[c + 1] : 0.f;
            #pragma unroll
            for (int eh = 0; eh < 2; eh++) {
                int r = m0 + mw * 32 + i * 16 + gid + 8 * eh;
                size_t base = (size_t)r * HDD + c;
                float v0 = acc[i][j][eh * 2 + 0] + b0;
                float v1 = acc[i][j][eh * 2 + 1] + b1;
                if (mode == 1) {
                    u16 h0, l0, h1, l1;
                    split_bf16(v0, h0, l0); split_bf16(v1, h1, l1);
                    *reinterpret_cast<uint32_t*>(C1h + base) = (uint32_t)h0 | ((uint32_t)h1 << 16);
                    *reinterpret_cast<uint32_t*>(C1l + base) = (uint32_t)l0 | ((uint32_t)l1 << 16);
                } else {
                    u16 h0, l0, h1, l1;
                    split_bf16(v0 + add1[c], h0, l0); split_bf16(v1 + add1[c + 1], h1, l1);
                    *reinterpret_cast<uint32_t*>(C1h + base) = (uint32_t)h0 | ((uint32_t)h1 << 16);
                    *reinterpret_cast<uint32_t*>(C1l + base) = (uint32_t)l0 | ((uint32_t)l1 << 16);
                    split_bf16(v0 + add2[c], h0, l0); split_bf16(v1 + add2[c + 1], h1, l1);
                    *reinterpret_cast<uint32_t*>(C2h + base) = (uint32_t)h0 | ((uint32_t)h1 << 16);
                    *reinterpret_cast<uint32_t*>(C2l + base) = (uint32_t)l0 | ((uint32_t)l1 << 16);
                }
            }
        }
}

// ---------------------------------------------------------------------------
// out-proj
// ---------------------------------------------------------------------------
__global__ void __launch_bounds__(256, 2)
outproj(const float* __restrict__ bo, float* __restrict__ Cf)
{
    extern __shared__ char sm[];
    const uint32_t sb = smem_u32(sm);
    const int tid = threadIdx.x, wid = tid >> 5, lane = tid & 31;
    const int mw = wid >> 1, nw = wid & 1;
    const int m0 = blockIdx.y << 7;
    const int n0 = blockIdx.x << 6;

    float acc[2][4][4] = {};
    gemm_core(sb, sm, tid, mw, nw, lane, g_vec_h, g_vec_l,
              g_w_h + WOO, g_w_l + WOO, m0, n0, HDD, acc);

    const int gid = lane >> 2, tg = lane & 3;
    #pragma unroll
    for (int i = 0; i < 2; i++)
        #pragma unroll
        for (int j = 0; j < 4; j++) {
            int c = n0 + nw * 32 + j * 8 + tg * 2;
            float b0 = bo[c], b1 = bo[c + 1];
            #pragma unroll
            for (int eh = 0; eh < 2; eh++) {
                int r = m0 + mw * 32 + i * 16 + gid + 8 * eh;
                *reinterpret_cast<float2*>(Cf + (size_t)r * EE + c) =
                    make_float2(acc[i][j][eh * 2 + 0] + b0, acc[i][j][eh * 2 + 1] + b1);
            }
        }
}

// ---------------------------------------------------------------------------
// tscore (R12 proven config): 256 threads / 8 warps (4m x 2n, n16 tiles),
// A' 128x128 resident, 32-key B tiles, 2-stage ring, 104.4KB smem, occ 2.
// ---------------------------------------------------------------------------
#define SP 272
#define TS_AHI 0
#define TS_ALO (128 * SP)
#define TS_B   (2 * 128 * SP)      // 69632
#define TS_BSTG (2 * 32 * SP)      // 17408
#define TS_BLOD (32 * SP)          // 8704
#define TS_TOTAL (TS_B + 2 * TS_BSTG)   // 104448
#define NKT 64                      // 64 key-tiles of 32

__global__ void __launch_bounds__(256, 2)
tscore()
{
    extern __shared__ char sm[];
    const uint32_t sb = smem_u32(sm);
    const int tid = threadIdx.x, wid = tid >> 5, lane = tid & 31;
    const int mw = wid >> 1, nw = wid & 1;
    const int gid = lane >> 2, tg = lane & 3;
    const int bh = blockIdx.z;
    const int b3 = bh / HH, h3 = bh % HH;
    const int mp = bh + BB;
    const int bu = mp / (HH + 1), hh = mp % (HH + 1);
    const int has_bd = (hh != 0);
    const int hm1 = hh - 1;
    const int q0 = blockIdx.y << 7;
    const int ksp = blockIdx.x;
    const int kt0 = (ksp * NKT) / 3, kt1 = ((ksp + 1) * NKT) / 3;

    #pragma unroll
    for (int it = 0; it < 8; it++) {
        int id = it * 256 + tid;
        int m = id >> 4, c = id & 15;
        uint4 hv, lv;
        if (c < 8) {
            size_t src = (size_t)(b3 * QLL + q0 + m) * HDD + h3 * DD + c * 8;
            hv = *reinterpret_cast<const uint4*>(g_qw_h + src);
            lv = *reinterpret_cast<const uint4*>(g_qw_l + src);
        } else if (has_bd) {
            size_t src = (size_t)(bu * QLL + q0 + m) * HDD + hm1 * DD + (c - 8) * 8;
            hv = *reinterpret_cast<const uint4*>(g_qr_h + src);
            lv = *reinterpret_cast<const uint4*>(g_qr_l + src);
        } else {
            hv = make_uint4(0u, 0u, 0u, 0u); lv = hv;
        }
        int off = m * SP + c * 16;
        *reinterpret_cast<uint4*>(sm + TS_AHI + off) = hv;
        *reinterpret_cast<uint4*>(sm + TS_ALO + off) = lv;
    }
    if (!has_bd) {
        uint4 z = make_uint4(0u, 0u, 0u, 0u);
        for (int id = tid; id < 32 * 8; id += 256) {
            int n = id >> 3, c = id & 7;
            int o = TS_B + n * SP + 128 + c * 16;
            *reinterpret_cast<uint4*>(sm + o) = z;
            *reinterpret_cast<uint4*>(sm + o + TS_BLOD) = z;
            *reinterpret_cast<uint4*>(sm + o + TS_BSTG) = z;
            *reinterpret_cast<uint4*>(sm + o + TS_BSTG + TS_BLOD) = z;
        }
    }

    auto issueB = [&](int kt, int st) {
        const uint32_t base = sb + TS_B + st * TS_BSTG;
        const int kc = kt << 5;
        const int nch = has_bd ? 16 : 8;
        const int tot = 32 * nch;
        for (int id = tid; id < tot; id += 256) {
            int n = id / nch, c = id % nch;
            uint32_t dst = base + n * SP + c * 16;
            if (c < 8) {
                size_t src = (size_t)(b3 * KLL + kc + n) * HDD + h3 * DD + c * 8;
                cpa16(dst, g_k_h + src);
                cpa16(dst + TS_BLOD, g_k_l + src);
            } else {
                size_t src = (size_t)(kc + n) * HDD + hm1 * DD + (c - 8) * 8;
                cpa16(dst, g_r_h + src);
                cpa16(dst + TS_BLOD, g_r_l + src);
            }
        }
    };

    issueB(kt0, 0); CP_COMMIT();

    for (int kt = kt0; kt < kt1; kt++) {
        const int stg = (kt - kt0) & 1;
        if (kt + 1 < kt1) { issueB(kt + 1, stg ^ 1); CP_COMMIT(); CP_WAIT(1); }
        else              { CP_WAIT(0); }
        __syncthreads();

        float acc[2][2][4] = {};
        const uint32_t bst = (uint32_t)(TS_B + stg * TS_BSTG);
        #pragma unroll
        for (int ks = 0; ks < 8; ks++)
            warp_mma_n16<SP>(sb, TS_AHI, TS_ALO, bst, bst + TS_BLOD,
                             ks << 4, mw, nw, lane, acc);

        const int kc = kt << 5;
        #pragma unroll
        for (int i = 0; i < 2; i++)
            #pragma unroll
            for (int j = 0; j < 2; j++) {
                int q = q0 + mw * 32 + i * 16 + gid;
                int c = kc + nw * 16 + j * 8 + tg * 2;
                const size_t srow0 = ((size_t)bh * QLL + q) * KLL + c;
                *reinterpret_cast<float2*>(g_s + srow0) =
                    make_float2(acc[i][j][0] * SCALEF, acc[i][j][1] * SCALEF);
                *reinterpret_cast<float2*>(g_s + srow0 + 8 * KLL) =
                    make_float2(acc[i][j][2] * SCALEF, acc[i][j][3] * SCALEF);
            }
        __syncthreads();
    }
}

// ---------------------------------------------------------------------------
// Softmax: reads int32 mask directly (streaming, HBM-roofline)
// ---------------------------------------------------------------------------
__device__ __forceinline__ float warp_max(float v) {
    #pragma unroll
    for (int o = 16; o; o >>= 1) v = fmaxf(v, __shfl_xor_sync(0xffffffffu, v, o));
    return v;
}
__device__ __forceinline__ float warp_sum(float v) {
    #pragma unroll
    for (int o = 16; o; o >>= 1) v += __shfl_xor_sync(0xffffffffu, v, o);
    return v;
}

__global__ __launch_bounds__(256)
void softmax_kernel(const float* __restrict__ S, float* __restrict__ P,
                    const mask_t* __restrict__ mask)
{
    const size_t row = blockIdx.x;
    const int b3 = (int)(row / (HH * QLL));
    const int q  = (int)(row % QLL);
    const float* s = S + row * KLL;
    float*       p = P + row * KLL;
    const int tid = threadIdx.x;

    __shared__ float sh[8];
    const int wid = tid >> 5;
    const int lid = tid & 31;

    const mask_t* mrow = mask + ((size_t)b3 * QLL + q) * KLL + tid * 8;
    int4 mk0 = *reinterpret_cast<const int4*>(mrow);
    int4 mk1 = *reinterpret_cast<const int4*>(mrow + 4);

    float v[8];
    *reinterpret_cast<float4*>(v)     = *reinterpret_cast<const float4*>(s + tid * 8);
    *reinterpret_cast<float4*>(v + 4) = *reinterpret_cast<const float4*>(s + tid * 8 + 4);

    if (mk0.x) v[0] = -3.0e38f;
    if (mk0.y) v[1] = -3.0e38f;
    if (mk0.z) v[2] = -3.0e38f;
    if (mk0.w) v[3] = -3.0e38f;
    if (mk1.x) v[4] = -3.0e38f;
    if (mk1.y) v[5] = -3.0e38f;
    if (mk1.z) v[6] = -3.0e38f;
    if (mk1.w) v[7] = -3.0e38f;

    float m = -3.0e38f;
    #pragma unroll
    for (int i = 0; i < 8; i++) m = fmaxf(m, v[i]);
    float wm = warp_max(m);
    if (lid == 0) sh[wid] = wm;
    __syncthreads();
    if (wid == 0) {
        float t = (lid < 8) ? sh[lid] : -3.0e38f;
        t = warp_max(t);
        if (lid == 0) sh[0] = t;
    }
    __syncthreads();
    const float bm = sh[0];

    float lsum = 0.0f;
    #pragma unroll
    for (int i = 0; i < 8; i++) {
        v[i] = __expf(v[i] - bm);
        lsum += v[i];
    }
    float ws = warp_sum(lsum);
    __syncthreads();
    if (lid == 0) sh[wid] = ws;
    __syncthreads();
    if (wid == 0) {
        float t = (lid < 8) ? sh[lid] : 0.0f;
        t = warp_sum(t);
        if (lid == 0) sh[0] = t;
    }
    __syncthreads();
    const float inv = 1.0f / sh[0];

    #pragma unroll
    for (int i = 0; i < 8; i++) v[i] *= inv;
    *reinterpret_cast<float4*>(p + tid * 8)     = *reinterpret_cast<float4*>(v);
    *reinterpret_cast<float4*>(p + tid * 8 + 4) = *reinterpret_cast<float4*>(v + 4);
}

// ---------------------------------------------------------------------------
// pv v2: prob staged via cp.async (raw fp32 -> smem), converted smem->smem,
// next tile's cp.async in flight during V-fill + MMA.  88KB smem, occ 2.
// ---------------------------------------------------------------------------
#define GP 144
#define PV_AHI 0
#define PV_ALO (128 * GP)                  // 18432
#define PV_BHI (2 * 128 * GP)              // 36864
#define PV_BLO (2 * 128 * GP + 64 * GP)    // 46080
#define PV_STG (2 * 128 * GP + 2 * 64 * GP)   // 55296 fp32 staging
#define PV_TOTAL (PV_STG + 128 * 64 * 4)      // 88064

__global__ void __launch_bounds__(256, 2)
pv_kernel(const float* __restrict__ prob)
{
    extern __shared__ char sm[];
    const uint32_t sb = smem_u32(sm);
    const int tid = threadIdx.x, wid = tid >> 5, lane = tid & 31;
    const int mw = wid >> 1, nw = wid & 1;
    const int bh = blockIdx.z;
    const int b3 = bh / HH, h3 = bh % HH;
    const int q0 = blockIdx.y << 7;
    const int ksp = blockIdx.x;
    const int kt0 = (ksp * 32) / 3, kt1 = ((ksp + 1) * 32) / 3;

    auto issueP = [&](int kt) {
        const int kc = kt << 6;
        // 128 rows x 16 chunks of 16B = 2048 cpa16 / 256 threads = 8 each
        #pragma unroll
        for (int it = 0; it < 8; it++) {
            int id = it * 256 + tid;
            int m = id >> 4, c = id & 15;
            const float* src = prob + ((size_t)bh * QLL + q0 + m) * KLL + kc + c * 4;
            uint32_t dst = sb + PV_STG + (uint32_t)((m * 64 + c * 4) * 4);
            cpa16(dst, src);
        }
    };

    float acc[2][4][4] = {};

    issueP(kt0); CP_COMMIT();

    for (int kt = kt0; kt < kt1; kt++) {
        CP_WAIT(0);
        __syncthreads();                 // stage holds prob tile kt; A/B free

        // convert stage (fp32) -> A bf16 hi/lo
        #pragma unroll
        for (int it = 0; it < 8; it++) {
            int id = it * 256 + tid;
            int m = id >> 4, c = id & 15;
            float4 p4 = *reinterpret_cast<const float4*>(sm + PV_STG + (m * 64 + c * 4) * 4);
            uint2 hi, lo; split4(p4, hi, lo);
            int off = m * GP + c * 8;
            *reinterpret_cast<uint2*>(sm + PV_AHI + off) = hi;
            *reinterpret_cast<uint2*>(sm + PV_ALO + off) = lo;
        }
        __syncthreads();                 // conversion done; stage reusable

        if (kt + 1 < kt1) { issueP(kt + 1); CP_COMMIT(); }   // flies during V-fill + MMA

        // V tile (sync loads, coalesced)
        const int kc = kt << 6;
        #pragma unroll
        for (int it = 0; it < 16; it++) {
            int idx = it * 256 + tid;
            int k = idx >> 6, n = idx & 63;
            size_t base = (size_t)(b3 * KLL + kc + k) * HDD + h3 * DD + n;
            int off = n * GP + k * 2;
            *reinterpret_cast<u16*>(sm + PV_BHI + off) = g_v_h[base];
            *reinterpret_cast<u16*>(sm + PV_BLO + off) = g_v_l[base];
        }
        __syncthreads();

        #pragma unroll
        for (int ks = 0; ks < 4; ks++)
            warp_mma<GP>(sb, PV_AHI, PV_ALO, PV_BHI, PV_BLO, ks << 4, mw, nw, lane, acc);
        __syncthreads();                 // A/B free for next iteration
    }

    float* dst = g_pv[ksp];
    const int gid = lane >> 2, tg = lane & 3;
    #pragma unroll
    for (int i = 0; i < 2; i++)
        #pragma unroll
        for (int j = 0; j < 4; j++) {
            int c = nw * 32 + j * 8 + tg * 2;
            #pragma unroll
            for (int eh = 0; eh < 2; eh++) {
                int q = q0 + mw * 32 + i * 16 + gid + 8 * eh;
                *reinterpret_cast<float2*>(
                    dst + (size_t)(b3 * QLL + q) * HDD + h3 * DD + c) =
                    make_float2(acc[i][j][eh * 2 + 0], acc[i][j][eh * 2 + 1]);
            }
        }
}

// ---------------------------------------------------------------------------
// Launch
// ---------------------------------------------------------------------------
extern "C" void kernel_launch(void* const* d_in, const int* in_sizes, int n_in,
                              void* d_out, int out_size)
{
    (void)in_sizes; (void)n_in; (void)out_size;

    const float*  Q    = (const float*)d_in[0];
    const float*  Kin  = (const float*)d_in[1];
    const float*  Vin  = (const float*)d_in[2];
    const float*  pos  = (const float*)d_in[3];
    const float*  rwb  = (const float*)d_in[4];
    const float*  rrb  = (const float*)d_in[5];
    const mask_t* mask = (const mask_t*)d_in[6];
    const float*  Wq = (const float*)d_in[8];
    const float*  bq = (const float*)d_in[9];
    const float*  Wk = (const float*)d_in[10];
    const float*  bk = (const float*)d_in[11];
    const float*  Wv = (const float*)d_in[12];
    const float*  bv = (const float*)d_in[13];
    const float*  Wr = (const float*)d_in[14];
    const float*  Wo = (const float*)d_in[15];
    const float*  bo = (const float*)d_in[16];

    float* out  = (float*)d_out;
    float* prob = out + (size_t)BB * QLL * EE;

    u16 *vech, *vecl;
    float *ps;
    cudaGetSymbolAddress((void**)&vech, g_vec_h);
    cudaGetSymbolAddress((void**)&vecl, g_vec_l);
    cudaGetSymbolAddress((void**)&ps,  g_s);

    cudaFuncSetAttribute(proj_all,  cudaFuncAttributeMaxDynamicSharedMemorySize, T2_TOTAL);
    cudaFuncSetAttribute(outproj,   cudaFuncAttributeMaxDynamicSharedMemorySize, T2_TOTAL);
    cudaFuncSetAttribute(tscore,    cudaFuncAttributeMaxDynamicSharedMemorySize, TS_TOTAL);
    cudaFuncSetAttribute(pv_kernel, cudaFuncAttributeMaxDynamicSharedMemorySize, PV_TOTAL);

    const dim3 blk(256);

    // Converts (2 launches)
    cvt_all<<<XTOT / 1024, blk>>>(Q, Kin, Vin, pos);
    cvtT_all<<<dim3(24, 24, 5), dim3(32, 8)>>>(Wq, Wk, Wv, Wr, Wo);

    // All four projections in one launch
    proj_all<<<dim3(12, 1, 96), blk, T2_TOTAL>>>(bq, bk, bv, rwb, rrb);

    // Scores (raw, scaled), 3-way k-split, occ-2 tscore (R12 config)
    tscore<<<dim3(3, QLL / 128, BB * HH), blk, TS_TOTAL>>>();

    // Softmax (mask read directly) -> prob
    softmax_kernel<<<BB * HH * QLL, blk>>>(ps, prob, mask);

    // PV (3-way k-split, cp.async staged prob) + reduce/split
    pv_kernel<<<dim3(3, QLL / 128, BB * HH), blk, PV_TOTAL>>>(prob);
    vecfin<<<(BB * QLL * HDD) / 1024, blk>>>(vech, vecl);

    // Output projection
    outproj<<<dim3(12, 16), blk, T2_TOTAL>>>(bo, out);
}